// round 1
// baseline (speedup 1.0000x reference)
#include <cuda_runtime.h>
#include <cstdint>
#include <cstddef>

#define Bn   64
#define Tn   1024
#define Dn   512
#define Hn   256
#define Gn   1024     /* 4*H */
#define NTOT 2048     /* both directions */
#define EPSC 0.001f

// ---------------- scratch (static device globals; allocation-free) ----------------
__device__ float    g_x[(size_t)Bn * Tn * Dn];        // 128 MB  normalized input
__device__ float    g_xg[(size_t)Bn * Tn * NTOT];     // 512 MB  xg for both dirs
__device__ float    g_hbuf[2][2][Bn * Hn];            // [parity][dir][b*H+j]
__device__ int      g_len[Bn];
__device__ unsigned g_flags[128];                     // [dir*64 + bs*8 + hs]

__device__ __forceinline__ float sigf(float x)  { return 1.0f / (1.0f + __expf(-x)); }
__device__ __forceinline__ float tanhf_(float x){ return 2.0f / (1.0f + __expf(-2.0f * x)) - 1.0f; }

// ---------------- init: zero the step-barrier flags (runs every graph replay) ------
__global__ void init_kernel() {
    if (threadIdx.x < 128) g_flags[threadIdx.x] = 0u;
}

// ---------------- lengths: L[b] = T - sum(pad[b,:]) -------------------------------
__global__ void lengths_kernel(const float* __restrict__ pads) {
    __shared__ float red[256];
    const int b = blockIdx.x;
    float s = 0.f;
    for (int t = threadIdx.x; t < Tn; t += 256) s += pads[b * Tn + t];
    red[threadIdx.x] = s;
    __syncthreads();
    for (int o = 128; o > 0; o >>= 1) {
        if (threadIdx.x < o) red[threadIdx.x] += red[threadIdx.x + o];
        __syncthreads();
    }
    if (threadIdx.x == 0) g_len[b] = Tn - (int)(red[0] + 0.5f);
}

// ---------------- BN + mask: x = ((in - mean)*inv + bias) * (1-pad) ---------------
__global__ void bn_kernel(const float* __restrict__ in, const float* __restrict__ pads,
                          const float* __restrict__ scale, const float* __restrict__ bias,
                          const float* __restrict__ mean, const float* __restrict__ var) {
    const int row = blockIdx.x;            // 0..65535 = b*T + t
    const int d   = threadIdx.x * 4;       // 128 threads * 4
    const float keep = 1.0f - pads[row];
    float4 v  = *(const float4*)(in + (size_t)row * Dn + d);
    float4 sc = *(const float4*)(scale + d);
    float4 bi = *(const float4*)(bias + d);
    float4 mu = *(const float4*)(mean + d);
    float4 va = *(const float4*)(var + d);
    float4 o;
    o.x = ((v.x - mu.x) * ((1.0f + sc.x) * rsqrtf(va.x + EPSC)) + bi.x) * keep;
    o.y = ((v.y - mu.y) * ((1.0f + sc.y) * rsqrtf(va.y + EPSC)) + bi.y) * keep;
    o.z = ((v.z - mu.z) * ((1.0f + sc.z) * rsqrtf(va.z + EPSC)) + bi.z) * keep;
    o.w = ((v.w - mu.w) * ((1.0f + sc.w) * rsqrtf(va.w + EPSC)) + bi.w) * keep;
    *(float4*)(g_x + (size_t)row * Dn + d) = o;
}

// ---------------- GEMM: g_xg[65536, 2048] = g_x[65536,512] @ [Wx_f | Wx_b] + bias --
// 128x128 tile, BK=8, 256 threads, 8x8 per thread (split 4+4), double-buffered smem.
__global__ void __launch_bounds__(256) gemm_kernel(const float* __restrict__ Wf,
                                                   const float* __restrict__ Wb,
                                                   const float* __restrict__ bf,
                                                   const float* __restrict__ bb) {
    __shared__ float As[2][8][128];
    __shared__ float Bs[2][8][128];

    const int tid = threadIdx.x;
    const int n0  = blockIdx.x * 128;           // 0..1920
    const int m0  = blockIdx.y * 128;
    const bool bwd = (n0 >= 1024);
    const float* W    = bwd ? Wb : Wf;
    const float* bias = bwd ? bb : bf;
    const int nl0 = bwd ? (n0 - 1024) : n0;

    const int arow = tid >> 1;                  // 0..127
    const int ak   = (tid & 1) * 4;             // 0 or 4
    const int brow = tid >> 5;                  // 0..7
    const int bn   = (tid & 31) * 4;

    const float* Aptr = g_x + (size_t)(m0 + arow) * Dn + ak;
    const float* Bptr = W + (size_t)brow * Gn + nl0 + bn;

    float4 av = *(const float4*)Aptr;
    float4 bv = *(const float4*)Bptr;
    As[0][ak + 0][arow] = av.x;
    As[0][ak + 1][arow] = av.y;
    As[0][ak + 2][arow] = av.z;
    As[0][ak + 3][arow] = av.w;
    *(float4*)&Bs[0][brow][bn] = bv;
    __syncthreads();

    const int tx = tid & 15, ty = tid >> 4;
    float acc[8][8];
#pragma unroll
    for (int i = 0; i < 8; i++)
#pragma unroll
        for (int j = 0; j < 8; j++) acc[i][j] = 0.f;

    int buf = 0;
    for (int kt = 0; kt < 64; kt++) {
        if (kt < 63) {
            av = *(const float4*)(Aptr + (kt + 1) * 8);
            bv = *(const float4*)(Bptr + (size_t)(kt + 1) * 8 * Gn);
        }
#pragma unroll
        for (int k = 0; k < 8; k++) {
            float4 a0 = *(const float4*)&As[buf][k][ty * 4];
            float4 a1 = *(const float4*)&As[buf][k][64 + ty * 4];
            float4 b0 = *(const float4*)&Bs[buf][k][tx * 4];
            float4 b1 = *(const float4*)&Bs[buf][k][64 + tx * 4];
            float a_[8] = {a0.x, a0.y, a0.z, a0.w, a1.x, a1.y, a1.z, a1.w};
            float b_[8] = {b0.x, b0.y, b0.z, b0.w, b1.x, b1.y, b1.z, b1.w};
#pragma unroll
            for (int i = 0; i < 8; i++)
#pragma unroll
                for (int j = 0; j < 8; j++) acc[i][j] += a_[i] * b_[j];
        }
        if (kt < 63) {
            As[buf ^ 1][ak + 0][arow] = av.x;
            As[buf ^ 1][ak + 1][arow] = av.y;
            As[buf ^ 1][ak + 2][arow] = av.z;
            As[buf ^ 1][ak + 3][arow] = av.w;
            *(float4*)&Bs[buf ^ 1][brow][bn] = bv;
            __syncthreads();
            buf ^= 1;
        }
    }

    float4 bias0 = *(const float4*)(bias + nl0 + tx * 4);
    float4 bias1 = *(const float4*)(bias + nl0 + 64 + tx * 4);
#pragma unroll
    for (int ri = 0; ri < 8; ri++) {
        const int rrow = m0 + ((ri < 4) ? (ty * 4 + ri) : (64 + ty * 4 + ri - 4));
        float4 o0 = {acc[ri][0] + bias0.x, acc[ri][1] + bias0.y,
                     acc[ri][2] + bias0.z, acc[ri][3] + bias0.w};
        float4 o1 = {acc[ri][4] + bias1.x, acc[ri][5] + bias1.y,
                     acc[ri][6] + bias1.z, acc[ri][7] + bias1.w};
        float* cp = g_xg + (size_t)rrow * NTOT + n0 + tx * 4;
        *(float4*)cp        = o0;
        *(float4*)(cp + 64) = o1;
    }
}

// ---------------- Recurrence: persistent, 128 CTAs = 2dir x 8bs x 8hs --------------
// CTA owns: batches [8*bs, 8*bs+8), hidden [32*hs, 32*hs+32)  (gate cols {j,256+j,512+j,768+j})
// Per step: gates = h @ Wh_slice + xg[row]; c,h update; h slice exchanged via L2 +
// release/acquire flag barrier among the 8 hidden-slice CTAs of the same (dir,bs).
#define HSTR 260
#define GSTR 132
#define REC_SMEM ((32768 + 8 * HSTR + 8 * GSTR + 256 + 8) * 4)

__global__ void __launch_bounds__(256, 1) recurrence_kernel(const float* __restrict__ Whf,
                                                            const float* __restrict__ Whb,
                                                            float* __restrict__ out) {
    extern __shared__ float sm[];
    float* Whs  = sm;                       // [256][128]  (k, c) c = gate*32 + jj
    float* h_sm = Whs + 32768;              // [8][HSTR]
    float* g_sm = h_sm + 8 * HSTR;          // [8][GSTR]
    float* c_sm = g_sm + 8 * GSTR;          // [8*32]
    int*   len_s = (int*)(c_sm + 256);      // [8]

    const int tid = threadIdx.x;
    const int bx  = blockIdx.x;
    const int dir = bx >> 6;
    const int hs  = bx & 7;
    const int bs  = (bx >> 3) & 7;
    const int j0  = hs * 32;
    const int b0  = bs * 8;
    const float* Wh = dir ? Whb : Whf;

    // load permuted Wh slice
    for (int idx = tid; idx < 32768; idx += 256) {
        const int k = idx >> 7, c = idx & 127;
        const int gate = c >> 5, jj = c & 31;
        Whs[idx] = Wh[(size_t)k * Gn + gate * Hn + j0 + jj];
    }
    if (tid < 8) len_s[tid] = g_len[b0 + tid];
    c_sm[tid] = 0.f;
    for (int idx = tid; idx < 8 * HSTR; idx += 256) h_sm[idx] = 0.f;
    __syncthreads();

    const int bq   = tid & 7;       // batch within slice (dot phase)
    const int c4q  = tid >> 3;      // 0..31 column quad
    const int cloc = c4q * 4;
    const int gate = cloc >> 5;
    const int gcol = gate * Hn + j0 + (cloc & 31);       // global gate column
    const float* xg_base = g_xg + dir * Gn + gcol;
    unsigned* myflag = &g_flags[dir * 64 + bs * 8 + hs];

    for (int t = 0; t < Tn; t++) {
        if (t > 0) {
            if (tid < 8) {
                const unsigned* fp = &g_flags[dir * 64 + bs * 8 + tid];
                unsigned v;
                do {
                    asm volatile("ld.acquire.gpu.u32 %0, [%1];" : "=r"(v) : "l"(fp) : "memory");
                } while (v < (unsigned)t);
            }
            __syncthreads();
            const float* hg = &g_hbuf[(t - 1) & 1][dir][0];
            for (int i = tid; i < 512; i += 256) {
                const int b = i >> 6;
                const int k4 = i & 63;
                float4 v = __ldcg((const float4*)(hg + (size_t)(b0 + b) * Hn + k4 * 4));
                *(float4*)(h_sm + b * HSTR + k4 * 4) = v;
            }
            __syncthreads();
        }

        // ---- dot: acc[4 cols] = h[bq,:] . Wh_slice[:, cloc..cloc+3]
        float4 acc = {0.f, 0.f, 0.f, 0.f};
        const float* wp = Whs + cloc;
        const float* hp = h_sm + bq * HSTR;
#pragma unroll 4
        for (int k4 = 0; k4 < 64; k4++) {
            const float4 hv = *(const float4*)(hp + k4 * 4);
            float4 w;
            w = *(const float4*)(wp + (k4 * 4 + 0) * 128);
            acc.x += w.x * hv.x; acc.y += w.y * hv.x; acc.z += w.z * hv.x; acc.w += w.w * hv.x;
            w = *(const float4*)(wp + (k4 * 4 + 1) * 128);
            acc.x += w.x * hv.y; acc.y += w.y * hv.y; acc.z += w.z * hv.y; acc.w += w.w * hv.y;
            w = *(const float4*)(wp + (k4 * 4 + 2) * 128);
            acc.x += w.x * hv.z; acc.y += w.y * hv.z; acc.z += w.z * hv.z; acc.w += w.w * hv.z;
            w = *(const float4*)(wp + (k4 * 4 + 3) * 128);
            acc.x += w.x * hv.w; acc.y += w.y * hv.w; acc.z += w.z * hv.w; acc.w += w.w * hv.w;
        }

        // ---- add xg (backward reads permuted row rt(t)) and stage gates
        {
            const int row = dir ? ((Tn - 1 - t + len_s[bq]) & (Tn - 1)) : t;
            const size_t rowg = (size_t)(b0 + bq) * Tn + row;
            const float4 xgv = __ldg((const float4*)(xg_base + rowg * NTOT));
            acc.x += xgv.x; acc.y += xgv.y; acc.z += xgv.z; acc.w += xgv.w;
            *(float4*)(g_sm + bq * GSTR + cloc) = acc;
        }
        __syncthreads();

        // ---- LSTM cell update: thread -> (b = tid>>5, j = tid&31)
        {
            const int b = tid >> 5, j = tid & 31;
            const float* gp = g_sm + b * GSTR + j;
            const float gi = gp[0], gf = gp[32], gg2 = gp[64], go = gp[96];
            float cc = sigf(gf) * c_sm[tid] + sigf(gi) * tanhf_(gg2);
            c_sm[tid] = cc;
            const float hh = sigf(go) * tanhf_(cc);

            g_hbuf[t & 1][dir][(size_t)(b0 + b) * Hn + j0 + j] = hh;

            const int opos = dir ? ((Tn - 1 - t + len_s[b]) & (Tn - 1)) : t;
            out[((size_t)(b0 + b) * Tn + opos) * (2 * Hn) + dir * Hn + j0 + j] = hh;
        }
        __threadfence();
        __syncthreads();
        if (tid == 0) {
            const unsigned nv = (unsigned)(t + 1);
            asm volatile("st.release.gpu.u32 [%0], %1;" ::"l"(myflag), "r"(nv) : "memory");
        }
    }
}

// ---------------- launch -----------------------------------------------------------
extern "C" void kernel_launch(void* const* d_in, const int* in_sizes, int n_in,
                              void* d_out, int out_size) {
    (void)in_sizes; (void)n_in; (void)out_size;
    const float* inputs   = (const float*)d_in[0];
    const float* pads     = (const float*)d_in[1];
    const float* bn_scale = (const float*)d_in[2];
    const float* bn_bias  = (const float*)d_in[3];
    const float* bn_mean  = (const float*)d_in[4];
    const float* bn_var   = (const float*)d_in[5];
    const float* Wx_f     = (const float*)d_in[6];
    const float* Wh_f     = (const float*)d_in[7];
    const float* b_f      = (const float*)d_in[8];
    const float* Wx_b     = (const float*)d_in[9];
    const float* Wh_b     = (const float*)d_in[10];
    const float* b_b      = (const float*)d_in[11];
    float* out = (float*)d_out;

    static bool inited = false;
    if (!inited) {
        cudaFuncSetAttribute(recurrence_kernel,
                             cudaFuncAttributeMaxDynamicSharedMemorySize, REC_SMEM);
        inited = true;
    }

    init_kernel<<<1, 128>>>();
    lengths_kernel<<<Bn, 256>>>(pads);
    bn_kernel<<<Bn * Tn, 128>>>(inputs, pads, bn_scale, bn_bias, bn_mean, bn_var);
    gemm_kernel<<<dim3(16, 512), 256>>>(Wx_f, Wx_b, b_f, b_b);
    recurrence_kernel<<<128, 256, REC_SMEM>>>(Wh_f, Wh_b, out);
}